// round 3
// baseline (speedup 1.0000x reference)
#include <cuda_runtime.h>
#include <math.h>

#define BB 32
#define NN 1024
#define KK 64
#define DD 1536
#define DCH 16            // d-dims per chunk
#define NCHK (DD / DCH)   // 96 chunks

typedef unsigned long long u64;

// ---------------- device scratch (no allocations allowed) ----------------
__device__ float g_cnorm[KK * DD];                    // normalized centers
__device__ int   g_labels[BB * NN];                   // argmax labels
__device__ float g_dinv[BB * NN];                     // per-descriptor 1/max(||d||,eps)
__device__ float g_vlad[(size_t)BB * KK * DD];        // intra-normalized vlad
__device__ float g_kssq[BB * KK];                     // per-(b,k) ||t||^2

union F2U { float2 f; u64 u; };

// Packed fp32x2 FMA (Blackwell sm_100+): 2 FMAs per issue slot.
__device__ __forceinline__ u64 ffma2(u64 a, u64 b, u64 c) {
#if defined(__CUDA_ARCH__) && (__CUDA_ARCH__ >= 1000)
    u64 d;
    asm("fma.rn.f32x2 %0, %1, %2, %3;" : "=l"(d) : "l"(a), "l"(b), "l"(c));
    return d;
#else
    F2U fa, fb, fc, fd;
    fa.u = a; fb.u = b; fc.u = c;
    fd.f.x = fmaf(fa.f.x, fb.f.x, fc.f.x);
    fd.f.y = fmaf(fa.f.y, fb.f.y, fc.f.y);
    return fd.u;
#endif
}

__device__ __forceinline__ u64 pack2(float x, float y) {
    F2U t; t.f = make_float2(x, y); return t.u;
}

// -------------------------------------------------------------------------
// K1: normalize cluster centers (c / max(||c||, eps))
// -------------------------------------------------------------------------
__global__ void k_centers(const float* __restrict__ cen) {
    int k = blockIdx.x, tid = threadIdx.x;
    float s = 0.f;
    for (int d = tid; d < DD; d += 256) {
        float v = cen[k * DD + d];
        s = fmaf(v, v, s);
    }
    __shared__ float red[9];
    #pragma unroll
    for (int o = 16; o > 0; o >>= 1) s += __shfl_xor_sync(0xffffffffu, s, o);
    if ((tid & 31) == 0) red[tid >> 5] = s;
    __syncthreads();
    if (tid < 32) {
        float t = (tid < 8) ? red[tid] : 0.f;
        #pragma unroll
        for (int o = 4; o > 0; o >>= 1) t += __shfl_xor_sync(0xffffffffu, t, o);
        if (tid == 0) red[8] = 1.0f / fmaxf(sqrtf(t), 1e-12f);
    }
    __syncthreads();
    float inv = red[8];
    for (int d = tid; d < DD; d += 256)
        g_cnorm[k * DD + d] = cen[k * DD + d] * inv;
}

// -------------------------------------------------------------------------
// K2: sims GEMM + argmax + per-row inverse norms.
// argmax_k <desc, cnorm_k> is invariant to the descriptor's positive scale,
// so raw descriptors feed the GEMM.  128 rows/block, 256 threads, 4x8
// register tile, f32x2 packed math, double-buffered SMEM staging with
// global->register prefetch.  Row ||.||^2 accumulated inline (+4 ffma2/p).
// -------------------------------------------------------------------------
__global__ __launch_bounds__(256, 2) void k_assign(const float* __restrict__ descs) {
    __shared__ __align__(16) u64 As[2][8][132];   // [buf][d-pair][row], padded
    __shared__ __align__(16) u64 Bs[2][8][68];    // [buf][d-pair][k],   padded
    __shared__ float pv[128][8];
    __shared__ int   pk[128][8];

    int tid  = threadIdx.x;
    int tcol = tid & 7;          // 8 center-groups of 8
    int trow = tid >> 3;         // 32 row-groups of 4
    size_t row0 = (size_t)blockIdx.x * 128;

    // global staging pointers (fixed row/seg per thread; advance by chunk)
    int idx0 = tid, idx1 = tid + 256;
    int r0 = idx0 >> 2, s0 = idx0 & 3;
    int r1 = idx1 >> 2, s1 = idx1 & 3;
    const float4* pa0 = (const float4*)(descs + (row0 + r0) * DD) + s0;
    const float4* pa1 = (const float4*)(descs + (row0 + r1) * DD) + s1;
    int kk = tid >> 2, sb = tid & 3;
    const float4* pb  = (const float4*)(g_cnorm + (size_t)kk * DD) + sb;

    u64 acc[4][8];
    u64 nrm[4];
    #pragma unroll
    for (int i = 0; i < 4; i++) {
        nrm[i] = 0ull;
        #pragma unroll
        for (int j = 0; j < 8; j++) acc[i][j] = 0ull;
    }

    // prefetch chunk 0 and stage into buffer 0
    float4 va0 = pa0[0], va1 = pa1[0], vb = pb[0];
    As[0][s0 * 2][r0]     = pack2(va0.x, va0.y);
    As[0][s0 * 2 + 1][r0] = pack2(va0.z, va0.w);
    As[0][s1 * 2][r1]     = pack2(va1.x, va1.y);
    As[0][s1 * 2 + 1][r1] = pack2(va1.z, va1.w);
    Bs[0][sb * 2][kk]     = pack2(vb.x, vb.y);
    Bs[0][sb * 2 + 1][kk] = pack2(vb.z, vb.w);

    for (int c = 0; c < NCHK; c++) {
        int buf = c & 1;
        __syncthreads();
        if (c + 1 < NCHK) {                    // issue next-chunk loads early
            va0 = pa0[(c + 1) * 4];
            va1 = pa1[(c + 1) * 4];
            vb  = pb[(c + 1) * 4];
        }
        #pragma unroll
        for (int p = 0; p < 8; p++) {
            u64 b[8];
            const ulonglong2* bp = (const ulonglong2*)&Bs[buf][p][tcol * 8];
            #pragma unroll
            for (int j = 0; j < 4; j++) { ulonglong2 t = bp[j]; b[2*j] = t.x; b[2*j+1] = t.y; }
            const ulonglong2* ap = (const ulonglong2*)&As[buf][p][trow * 4];
            ulonglong2 t0 = ap[0], t1 = ap[1];
            u64 a[4] = { t0.x, t0.y, t1.x, t1.y };
            #pragma unroll
            for (int i = 0; i < 4; i++) {
                nrm[i] = ffma2(a[i], a[i], nrm[i]);
                #pragma unroll
                for (int j = 0; j < 8; j++)
                    acc[i][j] = ffma2(a[i], b[j], acc[i][j]);
            }
        }
        if (c + 1 < NCHK) {                    // stage into the other buffer
            int nb = buf ^ 1;
            As[nb][s0 * 2][r0]     = pack2(va0.x, va0.y);
            As[nb][s0 * 2 + 1][r0] = pack2(va0.z, va0.w);
            As[nb][s1 * 2][r1]     = pack2(va1.x, va1.y);
            As[nb][s1 * 2 + 1][r1] = pack2(va1.z, va1.w);
            Bs[nb][sb * 2][kk]     = pack2(vb.x, vb.y);
            Bs[nb][sb * 2 + 1][kk] = pack2(vb.z, vb.w);
        }
    }

    // per-row inverse norms (each thread saw ALL d for its 4 rows)
    if (tcol == 0) {
        #pragma unroll
        for (int i = 0; i < 4; i++) {
            F2U t; t.u = nrm[i];
            float ssq = t.f.x + t.f.y;
            g_dinv[row0 + trow * 4 + i] = 1.0f / fmaxf(sqrtf(ssq), 1e-12f);
        }
    }

    // per-thread argmax over its 8 centers for each of its 4 rows
    #pragma unroll
    for (int i = 0; i < 4; i++) {
        float best = -3.4e38f; int bk = 0;
        #pragma unroll
        for (int j = 0; j < 8; j++) {
            F2U t; t.u = acc[i][j];
            float f = t.f.x + t.f.y;
            if (f > best) { best = f; bk = tcol * 8 + j; }
        }
        pv[trow * 4 + i][tcol] = best;
        pk[trow * 4 + i][tcol] = bk;
    }
    __syncthreads();
    if (tid < 128) {
        // c ascending => k ascending; strict '>' keeps lowest-k on ties
        float best = -3.4e38f; int bk = 0;
        #pragma unroll
        for (int c2 = 0; c2 < 8; c2++) {
            float f = pv[tid][c2];
            if (f > best) { best = f; bk = pk[tid][c2]; }
        }
        g_labels[row0 + tid] = bk;
    }
}

// -------------------------------------------------------------------------
// block-wide sum with broadcast (384 threads = 12 warps)
// -------------------------------------------------------------------------
__device__ __forceinline__ float blockSum384(float v, float* red) {
    #pragma unroll
    for (int o = 16; o > 0; o >>= 1) v += __shfl_xor_sync(0xffffffffu, v, o);
    if ((threadIdx.x & 31) == 0) red[threadIdx.x >> 5] = v;
    __syncthreads();
    if (threadIdx.x < 32) {
        float t = (threadIdx.x < 12) ? red[threadIdx.x] : 0.f;
        #pragma unroll
        for (int o = 8; o > 0; o >>= 1) t += __shfl_xor_sync(0xffffffffu, t, o);
        if (threadIdx.x == 0) red[12] = t;
    }
    __syncthreads();
    return red[12];
}

// -------------------------------------------------------------------------
// K3: per-(b,k) gather-aggregate.  Labels+dinv cached in SMEM, assignment
// list compacted by warp 0 (ballot/popc) -> branch-free streaming main loop
// with 1-ahead prefetch.  384 threads: one float4 (4 dims) per thread.
// -------------------------------------------------------------------------
__global__ __launch_bounds__(384) void k_agg(const float* __restrict__ descs,
                                             const float* __restrict__ cen) {
    int k = blockIdx.x, b = blockIdx.y, tid = threadIdx.x;
    __shared__ int   slab[NN];
    __shared__ float sdinv[NN];
    __shared__ int   list[NN];
    __shared__ int   s_cnt;
    __shared__ float red[13];

    for (int n = tid; n < NN; n += 384) {
        slab[n]  = g_labels[b * NN + n];
        sdinv[n] = g_dinv[b * NN + n];
    }
    __syncthreads();

    if (tid < 32) {
        int base = 0;
        #pragma unroll 4
        for (int i = 0; i < NN / 32; i++) {
            int n = i * 32 + tid;
            bool m = (slab[n] == k);
            unsigned msk = __ballot_sync(0xffffffffu, m);
            if (m) {
                int pos = __popc(msk & ((1u << tid) - 1u));
                list[base + pos] = n;
            }
            base += __popc(msk);
        }
        if (tid == 0) s_cnt = base;
    }
    __syncthreads();
    int cnt = s_cnt;

    const float4* base4 = (const float4*)descs + (size_t)b * NN * (DD / 4);
    float4 a = make_float4(0.f, 0.f, 0.f, 0.f);

    float4 vx; int n0 = 0;
    if (cnt > 0) { n0 = list[0]; vx = base4[(size_t)n0 * (DD / 4) + tid]; }
    for (int m = 0; m < cnt; m++) {
        float4 v = vx;
        float inv = sdinv[list[m]];
        if (m + 1 < cnt) {
            int nn = list[m + 1];
            vx = base4[(size_t)nn * (DD / 4) + tid];
        }
        a.x = fmaf(v.x, inv, a.x);
        a.y = fmaf(v.y, inv, a.y);
        a.z = fmaf(v.z, inv, a.z);
        a.w = fmaf(v.w, inv, a.w);
    }

    // un_vlad = sum - count * raw_center ; then intra-normalize
    float fc = (float)cnt;
    float4 c4 = ((const float4*)cen)[(size_t)k * (DD / 4) + tid];
    float4 u;
    u.x = a.x - fc * c4.x;
    u.y = a.y - fc * c4.y;
    u.z = a.z - fc * c4.z;
    u.w = a.w - fc * c4.w;

    float s = u.x * u.x + u.y * u.y + u.z * u.z + u.w * u.w;
    float tot = blockSum384(s, red);
    float inv = 1.0f / fmaxf(sqrtf(tot), 1e-12f);

    float4 o;
    o.x = u.x * inv; o.y = u.y * inv; o.z = u.z * inv; o.w = u.w * inv;
    ((float4*)g_vlad)[((size_t)b * KK + k) * (DD / 4) + tid] = o;

    if (tid == 0) g_kssq[b * KK + k] = tot * inv * inv;   // ||t_k||^2 (0 if empty)
}

// -------------------------------------------------------------------------
// K4: fused per-b global norm + scaled output write.
// grid (32 b, 8 slices); each block redundantly reduces its b's 64 kssq.
// -------------------------------------------------------------------------
__global__ void k_scale(float* __restrict__ out) {
    int b = blockIdx.x, part = blockIdx.y, tid = threadIdx.x;
    __shared__ float s_inv;
    if (tid < 32) {
        float v = g_kssq[b * KK + tid] + g_kssq[b * KK + 32 + tid];
        #pragma unroll
        for (int o = 16; o > 0; o >>= 1) v += __shfl_xor_sync(0xffffffffu, v, o);
        if (tid == 0) s_inv = 1.0f / fmaxf(sqrtf(v), 1e-12f);
    }
    __syncthreads();
    float inv = s_inv;

    const int per_b   = KK * DD / 4;       // 24576 float4
    const int per_blk = per_b / 8;         // 3072 float4
    size_t base = (size_t)b * per_b + (size_t)part * per_blk;
    #pragma unroll 4
    for (int i = tid; i < per_blk; i += 256) {
        float4 v = ((const float4*)g_vlad)[base + i];
        v.x *= inv; v.y *= inv; v.z *= inv; v.w *= inv;
        ((float4*)out)[base + i] = v;
    }
}

// -------------------------------------------------------------------------
extern "C" void kernel_launch(void* const* d_in, const int* in_sizes, int n_in,
                              void* d_out, int out_size) {
    const float* descs = (const float*)d_in[0];   // [B,N,D] fp32
    const float* cen   = (const float*)d_in[1];   // [K,D]   fp32
    float* out = (float*)d_out;                   // [B, K*D] fp32

    k_centers<<<KK, 256>>>(cen);
    k_assign<<<(BB * NN) / 128, 256>>>(descs);
    dim3 gagg(KK, BB);
    k_agg<<<gagg, 384>>>(descs, cen);
    dim3 gsc(BB, 8);
    k_scale<<<gsc, 256>>>(out);
}

// round 5
// speedup vs baseline: 1.6402x; 1.6402x over previous
#include <cuda_runtime.h>
#include <math.h>

#define BB 32
#define NN 1024
#define KK 64
#define DD 1536
#define DCH 16            // d-dims per chunk
#define NCHK (DD / DCH)   // 96 chunks

typedef unsigned long long u64;

// ---------------- device scratch (no allocations allowed) ----------------
__device__ float g_cnorm[KK * DD];                    // normalized centers
__device__ int   g_labels[BB * NN];                   // argmax labels
__device__ float g_dinv[BB * NN];                     // per-descriptor 1/max(||d||,eps)
__device__ float g_vlad[(size_t)BB * KK * DD];        // intra-normalized vlad
__device__ float g_kssq[BB * KK];                     // per-(b,k) ||t||^2

union F2U { float2 f; u64 u; };

// Packed fp32x2 FMA (Blackwell sm_100+): 2 FMAs per issue slot.
__device__ __forceinline__ u64 ffma2(u64 a, u64 b, u64 c) {
#if defined(__CUDA_ARCH__) && (__CUDA_ARCH__ >= 1000)
    u64 d;
    asm("fma.rn.f32x2 %0, %1, %2, %3;" : "=l"(d) : "l"(a), "l"(b), "l"(c));
    return d;
#else
    F2U fa, fb, fc, fd;
    fa.u = a; fb.u = b; fc.u = c;
    fd.f.x = fmaf(fa.f.x, fb.f.x, fc.f.x);
    fd.f.y = fmaf(fa.f.y, fb.f.y, fc.f.y);
    return fd.u;
#endif
}

__device__ __forceinline__ u64 pack2(float x, float y) {
    F2U t; t.f = make_float2(x, y); return t.u;
}

// -------------------------------------------------------------------------
// K1: normalize cluster centers (c / max(||c||, eps))
// -------------------------------------------------------------------------
__global__ void k_centers(const float* __restrict__ cen) {
    int k = blockIdx.x, tid = threadIdx.x;
    float s = 0.f;
    for (int d = tid; d < DD; d += 256) {
        float v = cen[k * DD + d];
        s = fmaf(v, v, s);
    }
    __shared__ float red[9];
    #pragma unroll
    for (int o = 16; o > 0; o >>= 1) s += __shfl_xor_sync(0xffffffffu, s, o);
    if ((tid & 31) == 0) red[tid >> 5] = s;
    __syncthreads();
    if (tid < 32) {
        float t = (tid < 8) ? red[tid] : 0.f;
        #pragma unroll
        for (int o = 4; o > 0; o >>= 1) t += __shfl_xor_sync(0xffffffffu, t, o);
        if (tid == 0) red[8] = 1.0f / fmaxf(sqrtf(t), 1e-12f);
    }
    __syncthreads();
    float inv = red[8];
    for (int d = tid; d < DD; d += 256)
        g_cnorm[k * DD + d] = cen[k * DD + d] * inv;
}

// -------------------------------------------------------------------------
// K2: sims GEMM + argmax + per-row inverse norms.
// argmax_k <desc, cnorm_k> is invariant to the descriptor's positive scale,
// so raw descriptors feed the GEMM.  256 rows/block, 256 threads, 8x8
// register tile (occ 1, ~200 regs — no reg cap: an occ-2 cap forces
// inner-loop spills and regresses).  Double-buffered SMEM staging with
// global->register prefetch, ONE sync per chunk.
// Row ||.||^2 accumulated inline (+1 ffma2 per row per p).
// -------------------------------------------------------------------------
__global__ __launch_bounds__(256, 1) void k_assign(const float* __restrict__ descs) {
    __shared__ __align__(16) u64 As[2][8][256];   // 32 KB
    __shared__ __align__(16) u64 Bs[2][8][64];    //  8 KB
    // pv/pk reuse As after the mainloop (behind a sync): 16 KB alias
    float* pv = (float*)&As[0][0][0];             // [256][8]
    int*   pk = (int*)(pv + 256 * 8);             // [256][8]

    int tid  = threadIdx.x;
    int tcol = tid & 7;          // 8 center-groups of 8
    int trow = tid >> 3;         // 32 row-groups of 8
    size_t row0 = (size_t)blockIdx.x * 256;

    // staging coordinates (fixed per thread; advance by chunk)
    int r0 = (tid          ) >> 2, s0 = (tid          ) & 3;
    int r1 = (tid + 256    ) >> 2, s1 = (tid + 256    ) & 3;
    int r2 = (tid + 512    ) >> 2, s2 = (tid + 512    ) & 3;
    int r3 = (tid + 768    ) >> 2, s3 = (tid + 768    ) & 3;
    const float4* pa0 = (const float4*)(descs + (row0 + r0) * DD) + s0;
    const float4* pa1 = (const float4*)(descs + (row0 + r1) * DD) + s1;
    const float4* pa2 = (const float4*)(descs + (row0 + r2) * DD) + s2;
    const float4* pa3 = (const float4*)(descs + (row0 + r3) * DD) + s3;
    int kk = tid >> 2, sb = tid & 3;
    const float4* pb  = (const float4*)(g_cnorm + (size_t)kk * DD) + sb;

    u64 acc[8][8];
    u64 nrm[8];
    #pragma unroll
    for (int i = 0; i < 8; i++) {
        nrm[i] = 0ull;
        #pragma unroll
        for (int j = 0; j < 8; j++) acc[i][j] = 0ull;
    }

    // stage chunk 0 into buffer 0
    {
        float4 va0 = pa0[0], va1 = pa1[0], va2 = pa2[0], va3 = pa3[0], vb = pb[0];
        As[0][s0*2][r0] = pack2(va0.x, va0.y); As[0][s0*2+1][r0] = pack2(va0.z, va0.w);
        As[0][s1*2][r1] = pack2(va1.x, va1.y); As[0][s1*2+1][r1] = pack2(va1.z, va1.w);
        As[0][s2*2][r2] = pack2(va2.x, va2.y); As[0][s2*2+1][r2] = pack2(va2.z, va2.w);
        As[0][s3*2][r3] = pack2(va3.x, va3.y); As[0][s3*2+1][r3] = pack2(va3.z, va3.w);
        Bs[0][sb*2][kk] = pack2(vb.x,  vb.y ); Bs[0][sb*2+1][kk] = pack2(vb.z,  vb.w );
    }

    for (int c = 0; c < NCHK; c++) {
        int buf = c & 1;
        __syncthreads();    // staging of buf done; previous compute on buf^1 done
        float4 va0, va1, va2, va3, vb;
        if (c + 1 < NCHK) {                    // issue next-chunk loads early
            va0 = pa0[(c + 1) * 4];
            va1 = pa1[(c + 1) * 4];
            va2 = pa2[(c + 1) * 4];
            va3 = pa3[(c + 1) * 4];
            vb  = pb [(c + 1) * 4];
        }
        #pragma unroll
        for (int p = 0; p < 8; p++) {
            u64 b[8];
            const ulonglong2* bp = (const ulonglong2*)&Bs[buf][p][tcol * 8];
            #pragma unroll
            for (int j = 0; j < 4; j++) { ulonglong2 t = bp[j]; b[2*j] = t.x; b[2*j+1] = t.y; }
            const ulonglong2* ap = (const ulonglong2*)&As[buf][p][trow * 8];
            #pragma unroll
            for (int i2 = 0; i2 < 4; i2++) {        // stream A two rows at a time
                ulonglong2 t = ap[i2];
                nrm[2*i2]   = ffma2(t.x, t.x, nrm[2*i2]);
                nrm[2*i2+1] = ffma2(t.y, t.y, nrm[2*i2+1]);
                #pragma unroll
                for (int j = 0; j < 8; j++) {
                    acc[2*i2][j]   = ffma2(t.x, b[j], acc[2*i2][j]);
                    acc[2*i2+1][j] = ffma2(t.y, b[j], acc[2*i2+1][j]);
                }
            }
        }
        if (c + 1 < NCHK) {                    // stage into the other buffer
            int nb = buf ^ 1;
            As[nb][s0*2][r0] = pack2(va0.x, va0.y); As[nb][s0*2+1][r0] = pack2(va0.z, va0.w);
            As[nb][s1*2][r1] = pack2(va1.x, va1.y); As[nb][s1*2+1][r1] = pack2(va1.z, va1.w);
            As[nb][s2*2][r2] = pack2(va2.x, va2.y); As[nb][s2*2+1][r2] = pack2(va2.z, va2.w);
            As[nb][s3*2][r3] = pack2(va3.x, va3.y); As[nb][s3*2+1][r3] = pack2(va3.z, va3.w);
            Bs[nb][sb*2][kk] = pack2(vb.x,  vb.y ); Bs[nb][sb*2+1][kk] = pack2(vb.z,  vb.w );
        }
    }

    // per-row inverse norms (each thread saw ALL d for its 8 rows)
    if (tcol == 0) {
        #pragma unroll
        for (int i = 0; i < 8; i++) {
            F2U t; t.u = nrm[i];
            float ssq = t.f.x + t.f.y;
            g_dinv[row0 + trow * 8 + i] = 1.0f / fmaxf(sqrtf(ssq), 1e-12f);
        }
    }

    __syncthreads();   // mainloop reads of As complete before pv/pk alias writes

    // per-thread argmax over its 8 centers for each of its 8 rows
    #pragma unroll
    for (int i = 0; i < 8; i++) {
        float best = -3.4e38f; int bk = 0;
        #pragma unroll
        for (int j = 0; j < 8; j++) {
            F2U t; t.u = acc[i][j];
            float f = t.f.x + t.f.y;
            if (f > best) { best = f; bk = tcol * 8 + j; }
        }
        pv[(trow * 8 + i) * 8 + tcol] = best;
        pk[(trow * 8 + i) * 8 + tcol] = bk;
    }
    __syncthreads();
    {
        // c2 ascending => k ascending; strict '>' keeps lowest-k on ties
        float best = -3.4e38f; int bk = 0;
        #pragma unroll
        for (int c2 = 0; c2 < 8; c2++) {
            float f = pv[tid * 8 + c2];
            if (f > best) { best = f; bk = pk[tid * 8 + c2]; }
        }
        g_labels[row0 + tid] = bk;
    }
}

// -------------------------------------------------------------------------
// block-wide sum with broadcast (384 threads = 12 warps)
// -------------------------------------------------------------------------
__device__ __forceinline__ float blockSum384(float v, float* red) {
    #pragma unroll
    for (int o = 16; o > 0; o >>= 1) v += __shfl_xor_sync(0xffffffffu, v, o);
    if ((threadIdx.x & 31) == 0) red[threadIdx.x >> 5] = v;
    __syncthreads();
    if (threadIdx.x < 32) {
        float t = (threadIdx.x < 12) ? red[threadIdx.x] : 0.f;
        #pragma unroll
        for (int o = 8; o > 0; o >>= 1) t += __shfl_xor_sync(0xffffffffu, t, o);
        if (threadIdx.x == 0) red[12] = t;
    }
    __syncthreads();
    return red[12];
}

// -------------------------------------------------------------------------
// K3: per-(b,k) gather-aggregate.  Labels+dinv cached in SMEM, assignment
// list compacted by warp 0 (ballot/popc) -> branch-free streaming main loop
// with 1-ahead prefetch.  384 threads: one float4 (4 dims) per thread.
// -------------------------------------------------------------------------
__global__ __launch_bounds__(384) void k_agg(const float* __restrict__ descs,
                                             const float* __restrict__ cen) {
    int k = blockIdx.x, b = blockIdx.y, tid = threadIdx.x;
    __shared__ int   slab[NN];
    __shared__ float sdinv[NN];
    __shared__ int   list[NN];
    __shared__ int   s_cnt;
    __shared__ float red[13];

    for (int n = tid; n < NN; n += 384) {
        slab[n]  = g_labels[b * NN + n];
        sdinv[n] = g_dinv[b * NN + n];
    }
    __syncthreads();

    if (tid < 32) {
        int base = 0;
        #pragma unroll 4
        for (int i = 0; i < NN / 32; i++) {
            int n = i * 32 + tid;
            bool m = (slab[n] == k);
            unsigned msk = __ballot_sync(0xffffffffu, m);
            if (m) {
                int pos = __popc(msk & ((1u << tid) - 1u));
                list[base + pos] = n;
            }
            base += __popc(msk);
        }
        if (tid == 0) s_cnt = base;
    }
    __syncthreads();
    int cnt = s_cnt;

    const float4* base4 = (const float4*)descs + (size_t)b * NN * (DD / 4);
    float4 a = make_float4(0.f, 0.f, 0.f, 0.f);

    float4 vx;
    if (cnt > 0) vx = base4[(size_t)list[0] * (DD / 4) + tid];
    for (int m = 0; m < cnt; m++) {
        float4 v = vx;
        float inv = sdinv[list[m]];
        if (m + 1 < cnt) vx = base4[(size_t)list[m + 1] * (DD / 4) + tid];
        a.x = fmaf(v.x, inv, a.x);
        a.y = fmaf(v.y, inv, a.y);
        a.z = fmaf(v.z, inv, a.z);
        a.w = fmaf(v.w, inv, a.w);
    }

    // un_vlad = sum - count * raw_center ; then intra-normalize
    float fc = (float)cnt;
    float4 c4 = ((const float4*)cen)[(size_t)k * (DD / 4) + tid];
    float4 u;
    u.x = a.x - fc * c4.x;
    u.y = a.y - fc * c4.y;
    u.z = a.z - fc * c4.z;
    u.w = a.w - fc * c4.w;

    float s = u.x * u.x + u.y * u.y + u.z * u.z + u.w * u.w;
    float tot = blockSum384(s, red);
    float inv = 1.0f / fmaxf(sqrtf(tot), 1e-12f);

    float4 o;
    o.x = u.x * inv; o.y = u.y * inv; o.z = u.z * inv; o.w = u.w * inv;
    ((float4*)g_vlad)[((size_t)b * KK + k) * (DD / 4) + tid] = o;

    if (tid == 0) g_kssq[b * KK + k] = tot * inv * inv;   // ||t_k||^2 (0 if empty)
}

// -------------------------------------------------------------------------
// K4: fused per-b global norm + scaled output write.
// One float4 per thread; 96 blocks per b (3072 blocks total) for full DRAM
// parallelism.  Each block redundantly warp-reduces its b's 64 kssq.
// -------------------------------------------------------------------------
__global__ void k_scale(float* __restrict__ out) {
    int gb = blockIdx.x;            // 0..3071
    int b = gb / 96;                // 96 blocks of 256 threads per image
    int part = gb - b * 96;
    int tid = threadIdx.x;
    __shared__ float s_inv;
    if (tid < 32) {
        float v = g_kssq[b * KK + tid] + g_kssq[b * KK + 32 + tid];
        #pragma unroll
        for (int o = 16; o > 0; o >>= 1) v += __shfl_xor_sync(0xffffffffu, v, o);
        if (tid == 0) s_inv = 1.0f / fmaxf(sqrtf(v), 1e-12f);
    }
    __syncthreads();
    float inv = s_inv;

    size_t i = (size_t)b * (KK * DD / 4) + (size_t)part * 256 + tid;
    float4 v = ((const float4*)g_vlad)[i];
    v.x *= inv; v.y *= inv; v.z *= inv; v.w *= inv;
    ((float4*)out)[i] = v;
}

// -------------------------------------------------------------------------
extern "C" void kernel_launch(void* const* d_in, const int* in_sizes, int n_in,
                              void* d_out, int out_size) {
    const float* descs = (const float*)d_in[0];   // [B,N,D] fp32
    const float* cen   = (const float*)d_in[1];   // [K,D]   fp32
    float* out = (float*)d_out;                   // [B, K*D] fp32

    k_centers<<<KK, 256>>>(cen);
    k_assign<<<(BB * NN) / 256, 256>>>(descs);
    dim3 gagg(KK, BB);
    k_agg<<<gagg, 384>>>(descs, cen);
    k_scale<<<3072, 256>>>(out);
}